// round 4
// baseline (speedup 1.0000x reference)
#include <cuda_runtime.h>
#include <cuda_bf16.h>

// Problem constants (fixed shapes per reference)
#define MDIM 16384          // B*L = 8*2048
#define NDIM 1024           // embed dim
#define KDIM 1024
#define LSEQ 2048
#define NHEADS 8
#define PDIM 128
#define RAD 7               // Gaussian truncation radius (tail < 3e-8 relative)

// Scratch: v and attended, 64 MB each (allowed: __device__ globals, no cudaMalloc)
__device__ float g_v[(size_t)MDIM * NDIM];
__device__ float g_att[(size_t)MDIM * NDIM];

typedef unsigned long long u64;

__device__ __forceinline__ u64 pack2(float x, float y) {
    u64 r; asm("mov.b64 %0, {%1, %2};" : "=l"(r) : "f"(x), "f"(y)); return r;
}
__device__ __forceinline__ void unpack2(u64 v, float& x, float& y) {
    asm("mov.b64 {%0, %1}, %2;" : "=f"(x), "=f"(y) : "l"(v));
}
// Packed fp32x2 FMA: d = a*b + d (per 32-bit lane). Doubles fp32 rate on sm_103a.
__device__ __forceinline__ void ffma2(u64& d, u64 a, u64 b) {
    asm("fma.rn.f32x2 %0, %1, %2, %0;" : "+l"(d) : "l"(a), "l"(b));
}

// ---------------------------------------------------------------------------
// SGEMM (NT):  C[m,n] = sum_k A[m,k] * B[n,k]
// A: [MDIM, KDIM] row-major, B: [NDIM, KDIM] row-major (i.e. C = A @ B^T)
// 128x128 block tile, BK=16, 256 threads, 8x8 microtile, f32x2 accumulators.
// ---------------------------------------------------------------------------
#define BM 128
#define BN 128
#define BK 16
#define SPAD 4

__global__ __launch_bounds__(256, 2)
void sgemm_nt(const float* __restrict__ A, const float* __restrict__ B,
              float* __restrict__ C)
{
    __shared__ float As[BK][BM + SPAD];   // transposed: As[k][m]
    __shared__ float Bs[BK][BN + SPAD];   // transposed: Bs[k][n]

    const int tid   = threadIdx.x;
    const int mBase = blockIdx.y * BM;
    const int nBase = blockIdx.x * BN;

    // load mapping: 128 rows x 16 k per tile, float4 along k.
    const int lr = tid >> 2;      // 0..63 (rows lr and lr+64)
    const int lc = tid & 3;       // 0..3  (k-chunk)
    const float* Ap = A + (size_t)(mBase + lr) * KDIM + lc * 4;
    const float* Bp = B + (size_t)(nBase + lr) * KDIM + lc * 4;

    // compute mapping
    const int trow = tid >> 4;    // 0..15 -> m sub-tile
    const int tcol = tid & 15;    // 0..15 -> n sub-tile

    u64 acc[8][4];
    #pragma unroll
    for (int i = 0; i < 8; i++) {
        #pragma unroll
        for (int j = 0; j < 4; j++) acc[i][j] = 0ULL;
    }

    for (int k0 = 0; k0 < KDIM; k0 += BK) {
        // global loads (issued before the barrier -> overlap previous compute)
        float4 a0 = *(const float4*)(Ap + k0);
        float4 a1 = *(const float4*)(Ap + k0 + (size_t)64 * KDIM);
        float4 b0 = *(const float4*)(Bp + k0);
        float4 b1 = *(const float4*)(Bp + k0 + (size_t)64 * KDIM);

        __syncthreads();   // previous tile's compute done before overwrite

        As[lc*4+0][lr]    = a0.x; As[lc*4+1][lr]    = a0.y;
        As[lc*4+2][lr]    = a0.z; As[lc*4+3][lr]    = a0.w;
        As[lc*4+0][lr+64] = a1.x; As[lc*4+1][lr+64] = a1.y;
        As[lc*4+2][lr+64] = a1.z; As[lc*4+3][lr+64] = a1.w;

        Bs[lc*4+0][lr]    = b0.x; Bs[lc*4+1][lr]    = b0.y;
        Bs[lc*4+2][lr]    = b0.z; Bs[lc*4+3][lr]    = b0.w;
        Bs[lc*4+0][lr+64] = b1.x; Bs[lc*4+1][lr+64] = b1.y;
        Bs[lc*4+2][lr+64] = b1.z; Bs[lc*4+3][lr+64] = b1.w;

        __syncthreads();

        #pragma unroll
        for (int kk = 0; kk < BK; kk++) {
            float4 av0 = *(const float4*)&As[kk][trow * 8];
            float4 av1 = *(const float4*)&As[kk][trow * 8 + 4];
            float4 bv0 = *(const float4*)&Bs[kk][tcol * 8];
            float4 bv1 = *(const float4*)&Bs[kk][tcol * 8 + 4];

            u64 bp0 = pack2(bv0.x, bv0.y);
            u64 bp1 = pack2(bv0.z, bv0.w);
            u64 bp2 = pack2(bv1.x, bv1.y);
            u64 bp3 = pack2(bv1.z, bv1.w);

            float am[8] = {av0.x, av0.y, av0.z, av0.w,
                           av1.x, av1.y, av1.z, av1.w};
            #pragma unroll
            for (int i = 0; i < 8; i++) {
                u64 ap = pack2(am[i], am[i]);
                ffma2(acc[i][0], ap, bp0);
                ffma2(acc[i][1], ap, bp1);
                ffma2(acc[i][2], ap, bp2);
                ffma2(acc[i][3], ap, bp3);
            }
        }
    }

    // epilogue: vectorized stores
    #pragma unroll
    for (int i = 0; i < 8; i++) {
        float o0, o1, o2, o3, o4, o5, o6, o7;
        unpack2(acc[i][0], o0, o1);
        unpack2(acc[i][1], o2, o3);
        unpack2(acc[i][2], o4, o5);
        unpack2(acc[i][3], o6, o7);
        float4* cp = (float4*)(C + (size_t)(mBase + trow * 8 + i) * NDIM
                                 + nBase + tcol * 8);
        cp[0] = make_float4(o0, o1, o2, o3);
        cp[1] = make_float4(o4, o5, o6, o7);
    }
}

// ---------------------------------------------------------------------------
// Analytic Gaussian attention == fixed 15-tap conv along seq, per head.
// Taps exp(-d^2/2) are compile-time constants (no expf, no MUFU traffic).
// Boundary renormalization matches the full-softmax reference exactly
// (tail beyond |d|=7 is < 3e-8 relative).
// ---------------------------------------------------------------------------
__device__ __forceinline__ float gw(int d) {
    int a = d < 0 ? -d : d;
    switch (a) {
        case 0: return 1.0f;
        case 1: return 0.60653065971e0f;
        case 2: return 0.13533528324e0f;
        case 3: return 1.11089965382e-2f;
        case 4: return 3.35462627903e-4f;
        case 5: return 3.72665317208e-6f;
        case 6: return 1.52299797447e-8f;
        default: return 2.28973484867e-11f;
    }
}

__global__ void conv_attn(const float* __restrict__ v, float* __restrict__ att)
{
    const int h  = blockIdx.y;
    const int b  = blockIdx.z;
    const int q  = blockIdx.x * blockDim.y + threadIdx.y;
    const int p4 = threadIdx.x;             // 0..31 -> float4 within head dim

    int c;
    switch (h) {
        case 0: case 5: c = q;        break;  // center
        case 1: case 6: c = q - 1;    break;  // left
        case 2: case 7: c = q + 1;    break;  // right
        case 3:         c = 0;        break;  // first
        default:        c = LSEQ - 1; break;  // last
    }

    float Z = 0.0f;
    #pragma unroll
    for (int d = -RAD; d <= RAD; d++) {
        int k = c + d;
        if (k >= 0 && k < LSEQ) Z += gw(d);
    }
    const float invZ = 1.0f / Z;

    const float* base = v + (size_t)b * LSEQ * NDIM + h * PDIM + p4 * 4;
    float4 acc = make_float4(0.f, 0.f, 0.f, 0.f);
    #pragma unroll
    for (int d = -RAD; d <= RAD; d++) {
        int k = c + d;
        if (k >= 0 && k < LSEQ) {
            float w = gw(d) * invZ;
            float4 vv = *(const float4*)(base + (size_t)k * NDIM);
            acc.x = fmaf(w, vv.x, acc.x);
            acc.y = fmaf(w, vv.y, acc.y);
            acc.z = fmaf(w, vv.z, acc.z);
            acc.w = fmaf(w, vv.w, acc.w);
        }
    }
    float4* op = (float4*)(att + ((size_t)b * LSEQ + q) * NDIM + h * PDIM + p4 * 4);
    *op = acc;
}

// ---------------------------------------------------------------------------
// kernel_launch: GEMM1 -> conv -> GEMM2   (all graph-capturable, no allocs)
// ---------------------------------------------------------------------------
extern "C" void kernel_launch(void* const* d_in, const int* in_sizes, int n_in,
                              void* d_out, int out_size)
{
    const float* x     = (const float*)d_in[0];
    const float* W_in  = (const float*)d_in[1];
    const float* W_out = (const float*)d_in[2];
    float* out = (float*)d_out;

    float *vbuf, *abuf;
    cudaGetSymbolAddress((void**)&vbuf, g_v);
    cudaGetSymbolAddress((void**)&abuf, g_att);

    dim3 ggrid(NDIM / BN, MDIM / BM);   // (8, 128)
    sgemm_nt<<<ggrid, 256>>>(x, W_in, vbuf);

    conv_attn<<<dim3(LSEQ / 8, NHEADS, 8), dim3(32, 8)>>>(vbuf, abuf);

    sgemm_nt<<<ggrid, 256>>>(abuf, W_out, out);
}

// round 6
// speedup vs baseline: 2.3968x; 2.3968x over previous
#include <cuda_runtime.h>
#include <cuda_bf16.h>
#include <cstdint>

// Problem constants
#define MDIM 16384          // B*L
#define NDIM 1024
#define KDIM 1024
#define LSEQ 2048
#define NHEADS 8
#define PDIM 128
#define RAD 7

// GEMM tiling
#define BT 128              // CTA tile (M and N)
#define KC 32               // k-chunk in bf16 elems
#define NKCH (KDIM / KC)    // 32
#define ROWB 80             // padded SMEM row bytes (64B data + 16B pad), 20-word stride
#define TILE_B (BT * ROWB)  // 10240 B per operand tile
#define AH_O 0
#define AL_O (1 * TILE_B)
#define BH_O (2 * TILE_B)
#define BL_O (3 * TILE_B)
#define STAGE_B (4 * TILE_B)          // 40960
#define SMEM_TOTAL (2 * STAGE_B)      // 81920

// ---------------- device scratch (no allocs allowed) ----------------
__device__ float         g_v  [(size_t)MDIM * NDIM];
__device__ __nv_bfloat16 g_xhi[(size_t)MDIM * KDIM];
__device__ __nv_bfloat16 g_xlo[(size_t)MDIM * KDIM];
__device__ __nv_bfloat16 g_ahi[(size_t)MDIM * KDIM];
__device__ __nv_bfloat16 g_alo[(size_t)MDIM * KDIM];
__device__ __nv_bfloat16 g_wih[(size_t)NDIM * KDIM];
__device__ __nv_bfloat16 g_wil[(size_t)NDIM * KDIM];
__device__ __nv_bfloat16 g_woh[(size_t)NDIM * KDIM];
__device__ __nv_bfloat16 g_wol[(size_t)NDIM * KDIM];

// ---------------- helpers ----------------
__device__ __forceinline__ uint32_t smem_u32(const void* p) {
    uint32_t a;
    asm("{ .reg .u64 t; cvta.to.shared.u64 t, %1; cvt.u32.u64 %0, t; }" : "=r"(a) : "l"(p));
    return a;
}
__device__ __forceinline__ void cp16(uint32_t dst, const void* src) {
    asm volatile("cp.async.cg.shared.global [%0], [%1], 16;" :: "r"(dst), "l"(src));
}
__device__ __forceinline__ void ldmx4(uint32_t* r, uint32_t addr) {
    asm volatile("ldmatrix.sync.aligned.m8n8.x4.shared.b16 {%0,%1,%2,%3}, [%4];"
                 : "=r"(r[0]), "=r"(r[1]), "=r"(r[2]), "=r"(r[3]) : "r"(addr));
}
__device__ __forceinline__ void mma16816(float* c, const uint32_t* a, const uint32_t* b) {
    asm volatile(
        "mma.sync.aligned.m16n8k16.row.col.f32.bf16.bf16.f32 "
        "{%0,%1,%2,%3}, {%4,%5,%6,%7}, {%8,%9}, {%0,%1,%2,%3};"
        : "+f"(c[0]), "+f"(c[1]), "+f"(c[2]), "+f"(c[3])
        : "r"(a[0]), "r"(a[1]), "r"(a[2]), "r"(a[3]), "r"(b[0]), "r"(b[1]));
}

// ---------------- bf16x3 GEMM via mma.sync (HMMA path) ----------------
// C[m,n] = sum_k (Ahi+Alo)[m,k] * (Bhi+Blo)[n,k]   (lo*lo dropped)
__global__ void __launch_bounds__(256, 2)
gemm_bf16x3(const __nv_bfloat16* __restrict__ ah, const __nv_bfloat16* __restrict__ al,
            const __nv_bfloat16* __restrict__ bh, const __nv_bfloat16* __restrict__ bl,
            float* __restrict__ C)
{
    extern __shared__ char smem[];
    const uint32_t sb = smem_u32(smem);
    const int tid = threadIdx.x;
    const int wid = tid >> 5, lane = tid & 31;
    const int mBase = blockIdx.y * BT, nBase = blockIdx.x * BT;
    const int warpM = wid & 1;        // 0..1  -> 64-row slab
    const int warpN = wid >> 1;       // 0..3  -> 32-col slab

    // ---- global->smem load mapping: 16B per thread per (array, half) ----
    const int lrow = tid >> 2;                 // 0..63
    const int lseg = tid & 3;                  // 16B segment within 64B row
    const uint32_t sdst = (uint32_t)lrow * ROWB + (uint32_t)lseg * 16;

    float acc[4][4][4];                        // [mf][nf][4]
#pragma unroll
    for (int i = 0; i < 4; i++)
#pragma unroll
        for (int j = 0; j < 4; j++)
#pragma unroll
            for (int k = 0; k < 4; k++) acc[i][j][k] = 0.f;

    // ---- ldmatrix source addresses (per-thread, stage-relative) ----
    // A: lanes 0-15 -> rows (lane&15), khalf = lane>>4
    const uint32_t a_addr = (uint32_t)((warpM * 64 + (lane & 15)) * ROWB + ((lane >> 4) * 16));
    // B: 4 groups of 8 lanes: (n0-7,h0),(n0-7,h1),(n8-15,h0),(n8-15,h1)
    const uint32_t b_row  = (uint32_t)(warpN * 32 + (lane & 7) + ((lane >> 4) << 3));
    const uint32_t b_addr = b_row * ROWB + (((lane >> 3) & 1) * 16);

    auto load_chunk = [&](uint32_t stage, int k0) {
        const char* pah = (const char*)(ah + (size_t)(mBase + lrow) * KDIM + k0) + lseg * 16;
        const char* pal = (const char*)(al + (size_t)(mBase + lrow) * KDIM + k0) + lseg * 16;
        const char* pbh = (const char*)(bh + (size_t)(nBase + lrow) * KDIM + k0) + lseg * 16;
        const char* pbl = (const char*)(bl + (size_t)(nBase + lrow) * KDIM + k0) + lseg * 16;
        const size_t rstep = (size_t)64 * KDIM * sizeof(__nv_bfloat16);
        cp16(stage + AH_O + sdst,            pah);
        cp16(stage + AH_O + sdst + 64*ROWB,  pah + rstep);
        cp16(stage + AL_O + sdst,            pal);
        cp16(stage + AL_O + sdst + 64*ROWB,  pal + rstep);
        cp16(stage + BH_O + sdst,            pbh);
        cp16(stage + BH_O + sdst + 64*ROWB,  pbh + rstep);
        cp16(stage + BL_O + sdst,            pbl);
        cp16(stage + BL_O + sdst + 64*ROWB,  pbl + rstep);
        asm volatile("cp.async.commit_group;" ::: "memory");
    };

    load_chunk(sb, 0);

    for (int ch = 0; ch < NKCH; ch++) {
        const uint32_t cur = sb + (uint32_t)(ch & 1) * STAGE_B;
        asm volatile("cp.async.wait_group 0;" ::: "memory");
        __syncthreads();
        if (ch + 1 < NKCH)
            load_chunk(sb + (uint32_t)((ch + 1) & 1) * STAGE_B, (ch + 1) * KC);

#pragma unroll
        for (int kk = 0; kk < 2; kk++) {       // two k16 steps per chunk
            const uint32_t ko = (uint32_t)kk * 32;
            uint32_t ahf[4][4], bhf[2][4], blf[2][4];
#pragma unroll
            for (int mf = 0; mf < 4; mf++)
                ldmx4(ahf[mf], cur + AH_O + a_addr + mf * 16 * ROWB + ko);
#pragma unroll
            for (int nf2 = 0; nf2 < 2; nf2++) {
                ldmx4(bhf[nf2], cur + BH_O + b_addr + nf2 * 16 * ROWB + ko);
                ldmx4(blf[nf2], cur + BL_O + b_addr + nf2 * 16 * ROWB + ko);
            }
            // hi*hi and hi*lo
#pragma unroll
            for (int mf = 0; mf < 4; mf++)
#pragma unroll
                for (int nf = 0; nf < 4; nf++) {
                    mma16816(acc[mf][nf], ahf[mf], &bhf[nf >> 1][(nf & 1) * 2]);
                    mma16816(acc[mf][nf], ahf[mf], &blf[nf >> 1][(nf & 1) * 2]);
                }
            // lo*hi (A_lo as transient fragment)
#pragma unroll
            for (int mf = 0; mf < 4; mf++) {
                uint32_t alf[4];
                ldmx4(alf, cur + AL_O + a_addr + mf * 16 * ROWB + ko);
#pragma unroll
                for (int nf = 0; nf < 4; nf++)
                    mma16816(acc[mf][nf], alf, &bhf[nf >> 1][(nf & 1) * 2]);
            }
        }
    }

    // ---- epilogue: direct float2 stores ----
    const int r0 = mBase + warpM * 64 + (lane >> 2);
    const int c0 = nBase + warpN * 32 + (lane & 3) * 2;
#pragma unroll
    for (int mf = 0; mf < 4; mf++)
#pragma unroll
        for (int nf = 0; nf < 4; nf++) {
            float* p = C + (size_t)(r0 + mf * 16) * NDIM + c0 + nf * 8;
            *(float2*)p                       = make_float2(acc[mf][nf][0], acc[mf][nf][1]);
            *(float2*)(p + (size_t)8 * NDIM)  = make_float2(acc[mf][nf][2], acc[mf][nf][3]);
        }
}

// ---------------- fp32 -> (bf16 hi, bf16 lo) split ----------------
__device__ __forceinline__ uint32_t pack_bf2(__nv_bfloat16 a, __nv_bfloat16 b) {
    return (uint32_t)__bfloat16_as_ushort(a) | ((uint32_t)__bfloat16_as_ushort(b) << 16);
}
__device__ __forceinline__ void split1(float x, __nv_bfloat16& h, __nv_bfloat16& l) {
    h = __float2bfloat16_rn(x);
    l = __float2bfloat16_rn(x - __bfloat162float(h));
}

__global__ void split_bf16(const float* __restrict__ in,
                           __nv_bfloat16* __restrict__ hi,
                           __nv_bfloat16* __restrict__ lo, int n4)
{
    int i = blockIdx.x * blockDim.x + threadIdx.x;
    if (i >= n4) return;
    float4 v = ((const float4*)in)[i];
    __nv_bfloat16 h0,h1,h2,h3,l0,l1,l2,l3;
    split1(v.x,h0,l0); split1(v.y,h1,l1); split1(v.z,h2,l2); split1(v.w,h3,l3);
    ((uint2*)hi)[i] = make_uint2(pack_bf2(h0,h1), pack_bf2(h2,h3));
    ((uint2*)lo)[i] = make_uint2(pack_bf2(l0,l1), pack_bf2(l2,l3));
}

// ---------------- analytic Gaussian attention = fixed 15-tap conv -------------
__device__ __forceinline__ float gw(int d) {
    int a = d < 0 ? -d : d;
    switch (a) {
        case 0: return 1.0f;
        case 1: return 0.60653065971e0f;
        case 2: return 0.13533528324e0f;
        case 3: return 1.11089965382e-2f;
        case 4: return 3.35462627903e-4f;
        case 5: return 3.72665317208e-6f;
        case 6: return 1.52299797447e-8f;
        default: return 2.28973484867e-11f;
    }
}

__global__ void conv_attn_split(const float* __restrict__ v,
                                __nv_bfloat16* __restrict__ ahi,
                                __nv_bfloat16* __restrict__ alo)
{
    const int h  = blockIdx.y;
    const int b  = blockIdx.z;
    const int q  = blockIdx.x * blockDim.y + threadIdx.y;
    const int p4 = threadIdx.x;

    int c;
    switch (h) {
        case 0: case 5: c = q;        break;
        case 1: case 6: c = q - 1;    break;
        case 2: case 7: c = q + 1;    break;
        case 3:         c = 0;        break;
        default:        c = LSEQ - 1; break;
    }

    float Z = 0.0f;
#pragma unroll
    for (int d = -RAD; d <= RAD; d++) {
        int k = c + d;
        if (k >= 0 && k < LSEQ) Z += gw(d);
    }
    const float invZ = 1.0f / Z;

    const float* base = v + (size_t)b * LSEQ * NDIM + h * PDIM + p4 * 4;
    float4 acc = make_float4(0.f, 0.f, 0.f, 0.f);
#pragma unroll
    for (int d = -RAD; d <= RAD; d++) {
        int k = c + d;
        if (k >= 0 && k < LSEQ) {
            float w = gw(d) * invZ;
            float4 vv = *(const float4*)(base + (size_t)k * NDIM);
            acc.x = fmaf(w, vv.x, acc.x);
            acc.y = fmaf(w, vv.y, acc.y);
            acc.z = fmaf(w, vv.z, acc.z);
            acc.w = fmaf(w, vv.w, acc.w);
        }
    }
    size_t oi = (((size_t)b * LSEQ + q) * NDIM + h * PDIM + p4 * 4) / 4; // uint2 idx
    __nv_bfloat16 h0,h1,h2,h3,l0,l1,l2,l3;
    split1(acc.x,h0,l0); split1(acc.y,h1,l1); split1(acc.z,h2,l2); split1(acc.w,h3,l3);
    ((uint2*)ahi)[oi] = make_uint2(pack_bf2(h0,h1), pack_bf2(h2,h3));
    ((uint2*)alo)[oi] = make_uint2(pack_bf2(l0,l1), pack_bf2(l2,l3));
}

// ---------------- launcher ----------------
extern "C" void kernel_launch(void* const* d_in, const int* in_sizes, int n_in,
                              void* d_out, int out_size)
{
    const float* x     = (const float*)d_in[0];
    const float* W_in  = (const float*)d_in[1];
    const float* W_out = (const float*)d_in[2];
    float* out = (float*)d_out;

    float *vp;
    __nv_bfloat16 *xh,*xl,*ah,*al,*wih,*wil,*woh,*wol;
    cudaGetSymbolAddress((void**)&vp,  g_v);
    cudaGetSymbolAddress((void**)&xh,  g_xhi);
    cudaGetSymbolAddress((void**)&xl,  g_xlo);
    cudaGetSymbolAddress((void**)&ah,  g_ahi);
    cudaGetSymbolAddress((void**)&al,  g_alo);
    cudaGetSymbolAddress((void**)&wih, g_wih);
    cudaGetSymbolAddress((void**)&wil, g_wil);
    cudaGetSymbolAddress((void**)&woh, g_woh);
    cudaGetSymbolAddress((void**)&wol, g_wol);

    cudaFuncSetAttribute(gemm_bf16x3, cudaFuncAttributeMaxDynamicSharedMemorySize, SMEM_TOTAL);

    const int nx4 = MDIM * KDIM / 4;
    const int nw4 = NDIM * KDIM / 4;
    split_bf16<<<(nx4 + 255) / 256, 256>>>(x,     xh, xl, nx4);
    split_bf16<<<(nw4 + 255) / 256, 256>>>(W_in,  wih, wil, nw4);
    split_bf16<<<(nw4 + 255) / 256, 256>>>(W_out, woh, wol, nw4);

    dim3 ggrid(NDIM / BT, MDIM / BT);   // (8, 128)
    gemm_bf16x3<<<ggrid, 256, SMEM_TOTAL>>>(xh, xl, wih, wil, vp);

    conv_attn_split<<<dim3(LSEQ / 8, NHEADS, 8), dim3(32, 8)>>>(vp, ah, al);

    gemm_bf16x3<<<ggrid, 256, SMEM_TOTAL>>>(ah, al, woh, wol, out);
}

// round 10
// speedup vs baseline: 3.3027x; 1.3780x over previous
#include <cuda_runtime.h>
#include <cuda_fp16.h>
#include <cstdint>

// Problem constants
#define MDIM 16384          // B*L
#define NDIM 1024
#define KDIM 1024
#define LSEQ 2048
#define NHEADS 8
#define PDIM 128
#define RAD 7

// GEMM tiling
#define BT 128              // CTA tile (M and N)
#define KC 32               // k-chunk in fp16 elems
#define NKCH (KDIM / KC)    // 32
#define ROWB 80             // padded SMEM row bytes (64B data + 16B pad)
#define TILE_B (BT * ROWB)  // 10240 B per operand tile
#define AH_O 0
#define AL_O (1 * TILE_B)
#define BH_O (2 * TILE_B)
#define STAGE_B (3 * TILE_B)          // 30720
#define NSTAGE 3
#define SMEM_TOTAL (NSTAGE * STAGE_B) // 92160

// ---------------- device scratch (no allocs allowed) ----------------
__device__ float  g_v  [(size_t)MDIM * NDIM];
__device__ __half g_xhi[(size_t)MDIM * KDIM];
__device__ __half g_xlo[(size_t)MDIM * KDIM];
__device__ __half g_ahi[(size_t)MDIM * KDIM];
__device__ __half g_alo[(size_t)MDIM * KDIM];
__device__ __half g_wih[(size_t)NDIM * KDIM];
__device__ __half g_woh[(size_t)NDIM * KDIM];

// ---------------- helpers ----------------
__device__ __forceinline__ uint32_t smem_u32(const void* p) {
    uint32_t a;
    asm("{ .reg .u64 t; cvta.to.shared.u64 t, %1; cvt.u32.u64 %0, t; }" : "=r"(a) : "l"(p));
    return a;
}
__device__ __forceinline__ void cp16(uint32_t dst, const void* src) {
    asm volatile("cp.async.cg.shared.global [%0], [%1], 16;" :: "r"(dst), "l"(src));
}
__device__ __forceinline__ void ldmx4(uint32_t* r, uint32_t addr) {
    asm volatile("ldmatrix.sync.aligned.m8n8.x4.shared.b16 {%0,%1,%2,%3}, [%4];"
                 : "=r"(r[0]), "=r"(r[1]), "=r"(r[2]), "=r"(r[3]) : "r"(addr));
}
__device__ __forceinline__ void mma16816(float* c, const uint32_t* a, const uint32_t* b) {
    asm volatile(
        "mma.sync.aligned.m16n8k16.row.col.f32.f16.f16.f32 "
        "{%0,%1,%2,%3}, {%4,%5,%6,%7}, {%8,%9}, {%0,%1,%2,%3};"
        : "+f"(c[0]), "+f"(c[1]), "+f"(c[2]), "+f"(c[3])
        : "r"(a[0]), "r"(a[1]), "r"(a[2]), "r"(a[3]), "r"(b[0]), "r"(b[1]));
}

// ---------------- fp16 2-pass GEMM via mma.sync (HMMA path) ----------------
// C[m,n] = sum_k (Ahi+Alo)[m,k] * Bhi[n,k]   (== A * B_hi exactly; dropped
// term is A*B_lo ~ 1.7e-4 rms-relative, far under tolerance)
__global__ void __launch_bounds__(256, 2)
gemm_f16x2(const __half* __restrict__ ah, const __half* __restrict__ al,
           const __half* __restrict__ bh, float* __restrict__ C)
{
    extern __shared__ char smem[];
    const uint32_t sb = smem_u32(smem);
    const int tid = threadIdx.x;
    const int wid = tid >> 5, lane = tid & 31;
    const int mBase = blockIdx.y * BT, nBase = blockIdx.x * BT;
    const int warpM = wid & 1;        // 0..1  -> 64-row slab
    const int warpN = wid >> 1;       // 0..3  -> 32-col slab

    // global->smem mapping: 16B per thread per (array, half-tile)
    const int lrow = tid >> 2;                 // 0..63
    const int lseg = tid & 3;                  // 16B segment within 64B row
    const uint32_t sdst = (uint32_t)lrow * ROWB + (uint32_t)lseg * 16;

    float acc[4][4][4];
#pragma unroll
    for (int i = 0; i < 4; i++)
#pragma unroll
        for (int j = 0; j < 4; j++)
#pragma unroll
            for (int k = 0; k < 4; k++) acc[i][j][k] = 0.f;

    // ldmatrix addresses (stage-relative)
    const uint32_t a_addr = (uint32_t)((warpM * 64 + (lane & 15)) * ROWB + ((lane >> 4) * 16));
    const uint32_t b_row  = (uint32_t)(warpN * 32 + (lane & 7) + ((lane >> 4) << 3));
    const uint32_t b_addr = b_row * ROWB + (((lane >> 3) & 1) * 16);

    auto load_chunk = [&](uint32_t stage, int k0) {
        const char* pah = (const char*)(ah + (size_t)(mBase + lrow) * KDIM + k0) + lseg * 16;
        const char* pal = (const char*)(al + (size_t)(mBase + lrow) * KDIM + k0) + lseg * 16;
        const char* pbh = (const char*)(bh + (size_t)(nBase + lrow) * KDIM + k0) + lseg * 16;
        const size_t rstep = (size_t)64 * KDIM * sizeof(__half);
        cp16(stage + AH_O + sdst,            pah);
        cp16(stage + AH_O + sdst + 64*ROWB,  pah + rstep);
        cp16(stage + AL_O + sdst,            pal);
        cp16(stage + AL_O + sdst + 64*ROWB,  pal + rstep);
        cp16(stage + BH_O + sdst,            pbh);
        cp16(stage + BH_O + sdst + 64*ROWB,  pbh + rstep);
        asm volatile("cp.async.commit_group;" ::: "memory");
    };

    // 3-stage pipeline prologue: chunks 0 and 1 in flight
    load_chunk(sb + 0 * STAGE_B, 0);
    load_chunk(sb + 1 * STAGE_B, KC);

    for (int ch = 0; ch < NKCH; ch++) {
        const uint32_t cur = sb + (uint32_t)(ch % NSTAGE) * STAGE_B;
        asm volatile("cp.async.wait_group 1;" ::: "memory");  // chunk ch resident
        __syncthreads();
        if (ch + 2 < NKCH)
            load_chunk(sb + (uint32_t)((ch + 2) % NSTAGE) * STAGE_B, (ch + 2) * KC);
        else
            asm volatile("cp.async.commit_group;" ::: "memory");  // keep group count invariant

#pragma unroll
        for (int kk = 0; kk < 2; kk++) {       // two k16 steps per chunk
            const uint32_t ko = (uint32_t)kk * 32;
            uint32_t ahf[4][4], alf[4][4], bhf[2][4];
#pragma unroll
            for (int mf = 0; mf < 4; mf++) {
                ldmx4(ahf[mf], cur + AH_O + a_addr + mf * 16 * ROWB + ko);
                ldmx4(alf[mf], cur + AL_O + a_addr + mf * 16 * ROWB + ko);
            }
#pragma unroll
            for (int nf2 = 0; nf2 < 2; nf2++)
                ldmx4(bhf[nf2], cur + BH_O + b_addr + nf2 * 16 * ROWB + ko);
#pragma unroll
            for (int mf = 0; mf < 4; mf++)
#pragma unroll
                for (int nf = 0; nf < 4; nf++) {
                    mma16816(acc[mf][nf], ahf[mf], &bhf[nf >> 1][(nf & 1) * 2]);
                    mma16816(acc[mf][nf], alf[mf], &bhf[nf >> 1][(nf & 1) * 2]);
                }
        }
    }

    // epilogue: direct float2 stores
    const int r0 = mBase + warpM * 64 + (lane >> 2);
    const int c0 = nBase + warpN * 32 + (lane & 3) * 2;
#pragma unroll
    for (int mf = 0; mf < 4; mf++)
#pragma unroll
        for (int nf = 0; nf < 4; nf++) {
            float* p = C + (size_t)(r0 + mf * 16) * NDIM + c0 + nf * 8;
            *(float2*)p                       = make_float2(acc[mf][nf][0], acc[mf][nf][1]);
            *(float2*)(p + (size_t)8 * NDIM)  = make_float2(acc[mf][nf][2], acc[mf][nf][3]);
        }
}

// ---------------- fp32 -> fp16 splits ----------------
__device__ __forceinline__ uint32_t pack_h2(__half a, __half b) {
    return (uint32_t)__half_as_ushort(a) | ((uint32_t)__half_as_ushort(b) << 16);
}
__device__ __forceinline__ void split1(float x, __half& h, __half& l) {
    h = __float2half_rn(x);
    l = __float2half_rn(x - __half2float(h));
}

__global__ void split_f16(const float* __restrict__ in,
                          __half* __restrict__ hi, __half* __restrict__ lo, int n4)
{
    int i = blockIdx.x * blockDim.x + threadIdx.x;
    if (i >= n4) return;
    float4 v = ((const float4*)in)[i];
    __half h0,h1,h2,h3,l0,l1,l2,l3;
    split1(v.x,h0,l0); split1(v.y,h1,l1); split1(v.z,h2,l2); split1(v.w,h3,l3);
    ((uint2*)hi)[i] = make_uint2(pack_h2(h0,h1), pack_h2(h2,h3));
    ((uint2*)lo)[i] = make_uint2(pack_h2(l0,l1), pack_h2(l2,l3));
}

__global__ void split_f16_hi(const float* __restrict__ in,
                             __half* __restrict__ hi, int n4)
{
    int i = blockIdx.x * blockDim.x + threadIdx.x;
    if (i >= n4) return;
    float4 v = ((const float4*)in)[i];
    ((uint2*)hi)[i] = make_uint2(
        pack_h2(__float2half_rn(v.x), __float2half_rn(v.y)),
        pack_h2(__float2half_rn(v.z), __float2half_rn(v.w)));
}

// ---------------- analytic Gaussian attention = fixed 15-tap conv -------------
__device__ __forceinline__ float gw(int d) {
    int a = d < 0 ? -d : d;
    switch (a) {
        case 0: return 1.0f;
        case 1: return 0.60653065971e0f;
        case 2: return 0.13533528324e0f;
        case 3: return 1.11089965382e-2f;
        case 4: return 3.35462627903e-4f;
        case 5: return 3.72665317208e-6f;
        case 6: return 1.52299797447e-8f;
        default: return 2.28973484867e-11f;
    }
}

__global__ void conv_attn_split(const float* __restrict__ v,
                                __half* __restrict__ ahi, __half* __restrict__ alo)
{
    const int h  = blockIdx.y;
    const int b  = blockIdx.z;
    const int q  = blockIdx.x * blockDim.y + threadIdx.y;
    const int p4 = threadIdx.x;

    int c;
    switch (h) {
        case 0: case 5: c = q;        break;
        case 1: case 6: c = q - 1;    break;
        case 2: case 7: c = q + 1;    break;
        case 3:         c = 0;        break;
        default:        c = LSEQ - 1; break;
    }

    float Z = 0.0f;
#pragma unroll
    for (int d = -RAD; d <= RAD; d++) {
        int k = c + d;
        if (k >= 0 && k < LSEQ) Z += gw(d);
    }
    const float invZ = 1.0f / Z;

    const float* base = v + (size_t)b * LSEQ * NDIM + h * PDIM + p4 * 4;
    float4 acc = make_float4(0.f, 0.f, 0.f, 0.f);
#pragma unroll
    for (int d = -RAD; d <= RAD; d++) {
        int k = c + d;
        if (k >= 0 && k < LSEQ) {
            float w = gw(d) * invZ;
            float4 vv = *(const float4*)(base + (size_t)k * NDIM);
            acc.x = fmaf(w, vv.x, acc.x);
            acc.y = fmaf(w, vv.y, acc.y);
            acc.z = fmaf(w, vv.z, acc.z);
            acc.w = fmaf(w, vv.w, acc.w);
        }
    }
    size_t oi = (((size_t)b * LSEQ + q) * NDIM + h * PDIM + p4 * 4) / 4; // uint2 idx
    __half h0,h1,h2,h3,l0,l1,l2,l3;
    split1(acc.x,h0,l0); split1(acc.y,h1,l1); split1(acc.z,h2,l2); split1(acc.w,h3,l3);
    ((uint2*)ahi)[oi] = make_uint2(pack_h2(h0,h1), pack_h2(h2,h3));
    ((uint2*)alo)[oi] = make_uint2(pack_h2(l0,l1), pack_h2(l2,l3));
}

// ---------------- launcher ----------------
extern "C" void kernel_launch(void* const* d_in, const int* in_sizes, int n_in,
                              void* d_out, int out_size)
{
    const float* x     = (const float*)d_in[0];
    const float* W_in  = (const float*)d_in[1];
    const float* W_out = (const float*)d_in[2];
    float* out = (float*)d_out;

    float *vp;
    __half *xh,*xl,*ah,*al,*wih,*woh;
    cudaGetSymbolAddress((void**)&vp,  g_v);
    cudaGetSymbolAddress((void**)&xh,  g_xhi);
    cudaGetSymbolAddress((void**)&xl,  g_xlo);
    cudaGetSymbolAddress((void**)&ah,  g_ahi);
    cudaGetSymbolAddress((void**)&al,  g_alo);
    cudaGetSymbolAddress((void**)&wih, g_wih);
    cudaGetSymbolAddress((void**)&woh, g_woh);

    cudaFuncSetAttribute(gemm_f16x2, cudaFuncAttributeMaxDynamicSharedMemorySize, SMEM_TOTAL);

    const int nx4 = MDIM * KDIM / 4;
    const int nw4 = NDIM * KDIM / 4;
    split_f16   <<<(nx4 + 255) / 256, 256>>>(x,     xh, xl, nx4);
    split_f16_hi<<<(nw4 + 255) / 256, 256>>>(W_in,  wih, nw4);
    split_f16_hi<<<(nw4 + 255) / 256, 256>>>(W_out, woh, nw4);

    dim3 ggrid(NDIM / BT, MDIM / BT);   // (8, 128)
    gemm_f16x2<<<ggrid, 256, SMEM_TOTAL>>>(xh, xl, wih, vp);

    conv_attn_split<<<dim3(LSEQ / 8, NHEADS, 8), dim3(32, 8)>>>(vp, ah, al);

    gemm_f16x2<<<ggrid, 256, SMEM_TOTAL>>>(ah, al, woh, out);
}

// round 12
// speedup vs baseline: 3.5025x; 1.0605x over previous
#include <cuda_runtime.h>
#include <cuda_fp16.h>
#include <cstdint>

// Problem constants
#define MDIM 16384          // B*L
#define NDIM 1024
#define KDIM 1024
#define LSEQ 2048
#define NHEADS 8
#define PDIM 128
#define RAD 7

// GEMM tiling
#define BT 128              // CTA tile (M and N)
#define KC 32               // k-chunk in fp16 elems
#define NKCH (KDIM / KC)    // 32
#define ROWB 80             // padded SMEM row bytes (64B data + 16B pad)
#define TILE_B (BT * ROWB)  // 10240 B per operand tile
#define A_O 0
#define B_O TILE_B
#define STAGE_B (2 * TILE_B)          // 20480
#define NSTAGE 4
#define SMEM_TOTAL (NSTAGE * STAGE_B) // 81920

// ---------------- device scratch (no allocs allowed) ----------------
__device__ float  g_v  [(size_t)MDIM * NDIM];
__device__ __half g_xh [(size_t)MDIM * KDIM];
__device__ __half g_ah [(size_t)MDIM * KDIM];
__device__ __half g_wih[(size_t)NDIM * KDIM];
__device__ __half g_woh[(size_t)NDIM * KDIM];

// ---------------- helpers ----------------
__device__ __forceinline__ uint32_t smem_u32(const void* p) {
    uint32_t a;
    asm("{ .reg .u64 t; cvta.to.shared.u64 t, %1; cvt.u32.u64 %0, t; }" : "=r"(a) : "l"(p));
    return a;
}
__device__ __forceinline__ void cp16(uint32_t dst, const void* src) {
    asm volatile("cp.async.cg.shared.global [%0], [%1], 16;" :: "r"(dst), "l"(src));
}
__device__ __forceinline__ void ldmx4(uint32_t* r, uint32_t addr) {
    asm volatile("ldmatrix.sync.aligned.m8n8.x4.shared.b16 {%0,%1,%2,%3}, [%4];"
                 : "=r"(r[0]), "=r"(r[1]), "=r"(r[2]), "=r"(r[3]) : "r"(addr));
}
__device__ __forceinline__ void mma16816(float* c, const uint32_t* a, const uint32_t* b) {
    asm volatile(
        "mma.sync.aligned.m16n8k16.row.col.f32.f16.f16.f32 "
        "{%0,%1,%2,%3}, {%4,%5,%6,%7}, {%8,%9}, {%0,%1,%2,%3};"
        : "+f"(c[0]), "+f"(c[1]), "+f"(c[2]), "+f"(c[3])
        : "r"(a[0]), "r"(a[1]), "r"(a[2]), "r"(a[3]), "r"(b[0]), "r"(b[1]));
}

// ---------------- single-pass fp16 GEMM via mma.sync (HMMA path) --------------
// C[m,n] = sum_k Ah[m,k] * Bh[n,k]  (fp32 accumulate; operand rounding only)
__global__ void __launch_bounds__(256, 2)
gemm_f16(const __half* __restrict__ ah, const __half* __restrict__ bh,
         float* __restrict__ C)
{
    extern __shared__ char smem[];
    const uint32_t sb = smem_u32(smem);
    const int tid = threadIdx.x;
    const int wid = tid >> 5, lane = tid & 31;
    const int mBase = blockIdx.y * BT, nBase = blockIdx.x * BT;
    const int warpM = wid & 1;        // 0..1  -> 64-row slab
    const int warpN = wid >> 1;       // 0..3  -> 32-col slab

    // global->smem mapping: 16B per thread per (array, half-tile)
    const int lrow = tid >> 2;                 // 0..63
    const int lseg = tid & 3;                  // 16B segment within 64B row
    const uint32_t sdst = (uint32_t)lrow * ROWB + (uint32_t)lseg * 16;

    float acc[4][4][4];
#pragma unroll
    for (int i = 0; i < 4; i++)
#pragma unroll
        for (int j = 0; j < 4; j++)
#pragma unroll
            for (int k = 0; k < 4; k++) acc[i][j][k] = 0.f;

    // ldmatrix addresses (stage-relative)
    const uint32_t a_addr = (uint32_t)((warpM * 64 + (lane & 15)) * ROWB + ((lane >> 4) * 16));
    const uint32_t b_row  = (uint32_t)(warpN * 32 + (lane & 7) + ((lane >> 4) << 3));
    const uint32_t b_addr = b_row * ROWB + (((lane >> 3) & 1) * 16);

    auto load_chunk = [&](uint32_t stage, int k0) {
        const char* pa = (const char*)(ah + (size_t)(mBase + lrow) * KDIM + k0) + lseg * 16;
        const char* pb = (const char*)(bh + (size_t)(nBase + lrow) * KDIM + k0) + lseg * 16;
        const size_t rstep = (size_t)64 * KDIM * sizeof(__half);
        cp16(stage + A_O + sdst,            pa);
        cp16(stage + A_O + sdst + 64*ROWB,  pa + rstep);
        cp16(stage + B_O + sdst,            pb);
        cp16(stage + B_O + sdst + 64*ROWB,  pb + rstep);
        asm volatile("cp.async.commit_group;" ::: "memory");
    };

    // 4-stage pipeline prologue: chunks 0..2 in flight
    load_chunk(sb + 0 * STAGE_B, 0);
    load_chunk(sb + 1 * STAGE_B, KC);
    load_chunk(sb + 2 * STAGE_B, 2 * KC);

    for (int ch = 0; ch < NKCH; ch++) {
        const uint32_t cur = sb + (uint32_t)(ch % NSTAGE) * STAGE_B;
        asm volatile("cp.async.wait_group 2;" ::: "memory");  // chunk ch resident
        __syncthreads();
        if (ch + 3 < NKCH)
            load_chunk(sb + (uint32_t)((ch + 3) % NSTAGE) * STAGE_B, (ch + 3) * KC);
        else
            asm volatile("cp.async.commit_group;" ::: "memory");  // keep group invariant

#pragma unroll
        for (int kk = 0; kk < 2; kk++) {       // two k16 steps per chunk
            const uint32_t ko = (uint32_t)kk * 32;
            uint32_t af[4][4], bf[2][4];
#pragma unroll
            for (int mf = 0; mf < 4; mf++)
                ldmx4(af[mf], cur + A_O + a_addr + mf * 16 * ROWB + ko);
#pragma unroll
            for (int nf2 = 0; nf2 < 2; nf2++)
                ldmx4(bf[nf2], cur + B_O + b_addr + nf2 * 16 * ROWB + ko);
#pragma unroll
            for (int mf = 0; mf < 4; mf++)
#pragma unroll
                for (int nf = 0; nf < 4; nf++)
                    mma16816(acc[mf][nf], af[mf], &bf[nf >> 1][(nf & 1) * 2]);
        }
    }

    // epilogue: direct float2 stores
    const int r0 = mBase + warpM * 64 + (lane >> 2);
    const int c0 = nBase + warpN * 32 + (lane & 3) * 2;
#pragma unroll
    for (int mf = 0; mf < 4; mf++)
#pragma unroll
        for (int nf = 0; nf < 4; nf++) {
            float* p = C + (size_t)(r0 + mf * 16) * NDIM + c0 + nf * 8;
            *(float2*)p                       = make_float2(acc[mf][nf][0], acc[mf][nf][1]);
            *(float2*)(p + (size_t)8 * NDIM)  = make_float2(acc[mf][nf][2], acc[mf][nf][3]);
        }
}

// ---------------- fp32 -> fp16 (round-to-nearest) ----------------
__device__ __forceinline__ uint32_t pack_h2(__half a, __half b) {
    return (uint32_t)__half_as_ushort(a) | ((uint32_t)__half_as_ushort(b) << 16);
}

__global__ void to_f16(const float* __restrict__ in, __half* __restrict__ hi, int n4)
{
    int i = blockIdx.x * blockDim.x + threadIdx.x;
    if (i >= n4) return;
    float4 v = ((const float4*)in)[i];
    ((uint2*)hi)[i] = make_uint2(
        pack_h2(__float2half_rn(v.x), __float2half_rn(v.y)),
        pack_h2(__float2half_rn(v.z), __float2half_rn(v.w)));
}

// ---------------- analytic Gaussian attention = fixed 15-tap conv -------------
__device__ __forceinline__ float gw(int d) {
    int a = d < 0 ? -d : d;
    switch (a) {
        case 0: return 1.0f;
        case 1: return 0.60653065971e0f;
        case 2: return 0.13533528324e0f;
        case 3: return 1.11089965382e-2f;
        case 4: return 3.35462627903e-4f;
        case 5: return 3.72665317208e-6f;
        case 6: return 1.52299797447e-8f;
        default: return 2.28973484867e-11f;
    }
}

__global__ void conv_attn_f16(const float* __restrict__ v, __half* __restrict__ att)
{
    const int h  = blockIdx.y;
    const int b  = blockIdx.z;
    const int q  = blockIdx.x * blockDim.y + threadIdx.y;
    const int p4 = threadIdx.x;

    int c;
    switch (h) {
        case 0: case 5: c = q;        break;
        case 1: case 6: c = q - 1;    break;
        case 2: case 7: c = q + 1;    break;
        case 3:         c = 0;        break;
        default:        c = LSEQ - 1; break;
    }

    float Z = 0.0f;
#pragma unroll
    for (int d = -RAD; d <= RAD; d++) {
        int k = c + d;
        if (k >= 0 && k < LSEQ) Z += gw(d);
    }
    const float invZ = 1.0f / Z;

    const float* base = v + (size_t)b * LSEQ * NDIM + h * PDIM + p4 * 4;
    float4 acc = make_float4(0.f, 0.f, 0.f, 0.f);
#pragma unroll
    for (int d = -RAD; d <= RAD; d++) {
        int k = c + d;
        if (k >= 0 && k < LSEQ) {
            float w = gw(d) * invZ;
            float4 vv = *(const float4*)(base + (size_t)k * NDIM);
            acc.x = fmaf(w, vv.x, acc.x);
            acc.y = fmaf(w, vv.y, acc.y);
            acc.z = fmaf(w, vv.z, acc.z);
            acc.w = fmaf(w, vv.w, acc.w);
        }
    }
    size_t oi = (((size_t)b * LSEQ + q) * NDIM + h * PDIM + p4 * 4) / 4; // uint2 idx
    ((uint2*)att)[oi] = make_uint2(
        pack_h2(__float2half_rn(acc.x), __float2half_rn(acc.y)),
        pack_h2(__float2half_rn(acc.z), __float2half_rn(acc.w)));
}

// ---------------- launcher ----------------
extern "C" void kernel_launch(void* const* d_in, const int* in_sizes, int n_in,
                              void* d_out, int out_size)
{
    const float* x     = (const float*)d_in[0];
    const float* W_in  = (const float*)d_in[1];
    const float* W_out = (const float*)d_in[2];
    float* out = (float*)d_out;

    float *vp;
    __half *xh,*ah,*wih,*woh;
    cudaGetSymbolAddress((void**)&vp,  g_v);
    cudaGetSymbolAddress((void**)&xh,  g_xh);
    cudaGetSymbolAddress((void**)&ah,  g_ah);
    cudaGetSymbolAddress((void**)&wih, g_wih);
    cudaGetSymbolAddress((void**)&woh, g_woh);

    cudaFuncSetAttribute(gemm_f16, cudaFuncAttributeMaxDynamicSharedMemorySize, SMEM_TOTAL);

    const int nx4 = MDIM * KDIM / 4;
    const int nw4 = NDIM * KDIM / 4;
    to_f16<<<(nx4 + 255) / 256, 256>>>(x,     xh,  nx4);
    to_f16<<<(nw4 + 255) / 256, 256>>>(W_in,  wih, nw4);
    to_f16<<<(nw4 + 255) / 256, 256>>>(W_out, woh, nw4);

    dim3 ggrid(NDIM / BT, MDIM / BT);   // (8, 128)
    gemm_f16<<<ggrid, 256, SMEM_TOTAL>>>(xh, wih, vp);

    conv_attn_f16<<<dim3(LSEQ / 8, NHEADS, 8), dim3(32, 8)>>>(vp, ah);

    gemm_f16<<<ggrid, 256, SMEM_TOTAL>>>(ah, woh, out);
}

// round 13
// speedup vs baseline: 5.5162x; 1.5749x over previous
#include <cuda_runtime.h>
#include <cuda_fp16.h>
#include <cstdint>

// Problem constants
#define MDIM 16384          // B*L
#define NDIM 1024
#define KDIM 1024
#define LSEQ 2048
#define NHEADS 8
#define PDIM 128
#define RAD 7

// GEMM tiling: CTA 128x128, 4 warps (2x2), warp tile 64x64
#define BT 128
#define KC 32               // k-chunk in fp16 elems
#define NKCH (KDIM / KC)    // 32
#define ROWB 80             // padded SMEM row bytes (64B data + 16B pad)
#define TILE_B (BT * ROWB)  // 10240 B per operand tile
#define A_O 0
#define B_O TILE_B
#define STAGE_B (2 * TILE_B)          // 20480
#define NSTAGE 4
#define SMEM_TOTAL (NSTAGE * STAGE_B) // 81920 (x2 CTAs = 160KB/SM, fits 228KB)

// ---------------- device scratch (no allocs allowed) ----------------
__device__ __half g_vh [(size_t)MDIM * NDIM];   // v in fp16
__device__ __half g_xh [(size_t)MDIM * KDIM];
__device__ __half g_ah [(size_t)MDIM * KDIM];
__device__ __half g_wih[(size_t)NDIM * KDIM];
__device__ __half g_woh[(size_t)NDIM * KDIM];

// ---------------- helpers ----------------
__device__ __forceinline__ uint32_t smem_u32(const void* p) {
    uint32_t a;
    asm("{ .reg .u64 t; cvta.to.shared.u64 t, %1; cvt.u32.u64 %0, t; }" : "=r"(a) : "l"(p));
    return a;
}
__device__ __forceinline__ void cp16(uint32_t dst, const void* src) {
    asm volatile("cp.async.cg.shared.global [%0], [%1], 16;" :: "r"(dst), "l"(src));
}
__device__ __forceinline__ void ldmx4(uint32_t* r, uint32_t addr) {
    asm volatile("ldmatrix.sync.aligned.m8n8.x4.shared.b16 {%0,%1,%2,%3}, [%4];"
                 : "=r"(r[0]), "=r"(r[1]), "=r"(r[2]), "=r"(r[3]) : "r"(addr));
}
__device__ __forceinline__ void mma16816(float* c, const uint32_t* a, const uint32_t* b) {
    asm volatile(
        "mma.sync.aligned.m16n8k16.row.col.f32.f16.f16.f32 "
        "{%0,%1,%2,%3}, {%4,%5,%6,%7}, {%8,%9}, {%0,%1,%2,%3};"
        : "+f"(c[0]), "+f"(c[1]), "+f"(c[2]), "+f"(c[3])
        : "r"(a[0]), "r"(a[1]), "r"(a[2]), "r"(a[3]), "r"(b[0]), "r"(b[1]));
}

// ---------------- single-pass fp16 GEMM, 64x64 warp tile ----------------------
// C[m,n] = sum_k Ah[m,k] * Bh[n,k]  (fp32 accumulate)
template <typename OT>
__global__ void __launch_bounds__(128, 2)
gemm_f16(const __half* __restrict__ ah, const __half* __restrict__ bh,
         OT* __restrict__ C)
{
    extern __shared__ char smem[];
    const uint32_t sb = smem_u32(smem);
    const int tid = threadIdx.x;
    const int wid = tid >> 5, lane = tid & 31;
    const int mBase = blockIdx.y * BT, nBase = blockIdx.x * BT;
    const int warpM = wid & 1;        // 0..1 -> 64-row slab
    const int warpN = wid >> 1;       // 0..1 -> 64-col slab

    // global->smem mapping: 8 cp16 per thread per chunk (A 4 rows, B 4 rows)
    const int lrow = tid >> 2;                 // 0..31
    const int lseg = tid & 3;                  // 16B segment within 64B row
    const uint32_t sdst = (uint32_t)lrow * ROWB + (uint32_t)lseg * 16;

    float acc[4][8][4];                        // 64x64 per warp = 128 regs
#pragma unroll
    for (int i = 0; i < 4; i++)
#pragma unroll
        for (int j = 0; j < 8; j++)
#pragma unroll
            for (int k = 0; k < 4; k++) acc[i][j][k] = 0.f;

    // ldmatrix addresses (stage-relative)
    const uint32_t a_addr = (uint32_t)((warpM * 64 + (lane & 15)) * ROWB + ((lane >> 4) * 16));
    const uint32_t b_row  = (uint32_t)(warpN * 64 + (lane & 7) + ((lane >> 4) << 3));
    const uint32_t b_addr = b_row * ROWB + (((lane >> 3) & 1) * 16);

    auto load_chunk = [&](uint32_t stage, int k0) {
        const char* pa = (const char*)(ah + (size_t)(mBase + lrow) * KDIM + k0) + lseg * 16;
        const char* pb = (const char*)(bh + (size_t)(nBase + lrow) * KDIM + k0) + lseg * 16;
        const size_t rstep = (size_t)32 * KDIM * sizeof(__half);
#pragma unroll
        for (int p = 0; p < 4; p++) {
            cp16(stage + A_O + sdst + p * 32 * ROWB, pa + p * rstep);
            cp16(stage + B_O + sdst + p * 32 * ROWB, pb + p * rstep);
        }
        asm volatile("cp.async.commit_group;" ::: "memory");
    };

    // 4-stage pipeline prologue: chunks 0..2 in flight
    load_chunk(sb + 0 * STAGE_B, 0);
    load_chunk(sb + 1 * STAGE_B, KC);
    load_chunk(sb + 2 * STAGE_B, 2 * KC);

    for (int ch = 0; ch < NKCH; ch++) {
        const uint32_t cur = sb + (uint32_t)(ch % NSTAGE) * STAGE_B;
        asm volatile("cp.async.wait_group 2;" ::: "memory");  // chunk ch resident
        __syncthreads();
        if (ch + 3 < NKCH)
            load_chunk(sb + (uint32_t)((ch + 3) % NSTAGE) * STAGE_B, (ch + 3) * KC);
        else
            asm volatile("cp.async.commit_group;" ::: "memory");  // keep group invariant

#pragma unroll
        for (int kk = 0; kk < 2; kk++) {       // two k16 steps per chunk
            const uint32_t ko = (uint32_t)kk * 32;
            uint32_t af[4][4], bf[4][4];
#pragma unroll
            for (int mf = 0; mf < 4; mf++)
                ldmx4(af[mf], cur + A_O + a_addr + mf * 16 * ROWB + ko);
#pragma unroll
            for (int nf2 = 0; nf2 < 4; nf2++)
                ldmx4(bf[nf2], cur + B_O + b_addr + nf2 * 16 * ROWB + ko);
#pragma unroll
            for (int mf = 0; mf < 4; mf++)
#pragma unroll
                for (int nf = 0; nf < 8; nf++)
                    mma16816(acc[mf][nf], af[mf], &bf[nf >> 1][(nf & 1) * 2]);
        }
    }

    // epilogue
    const int r0 = mBase + warpM * 64 + (lane >> 2);
    const int c0 = nBase + warpN * 64 + (lane & 3) * 2;
#pragma unroll
    for (int mf = 0; mf < 4; mf++)
#pragma unroll
        for (int nf = 0; nf < 8; nf++) {
            if constexpr (sizeof(OT) == 4) {
                float* p = (float*)C + (size_t)(r0 + mf * 16) * NDIM + c0 + nf * 8;
                *(float2*)p                      = make_float2(acc[mf][nf][0], acc[mf][nf][1]);
                *(float2*)(p + (size_t)8 * NDIM) = make_float2(acc[mf][nf][2], acc[mf][nf][3]);
            } else {
                __half* p = (__half*)C + (size_t)(r0 + mf * 16) * NDIM + c0 + nf * 8;
                *(__half2*)p                      = __floats2half2_rn(acc[mf][nf][0], acc[mf][nf][1]);
                *(__half2*)(p + (size_t)8 * NDIM) = __floats2half2_rn(acc[mf][nf][2], acc[mf][nf][3]);
            }
        }
}

// ---------------- fp32 -> fp16 (round-to-nearest) ----------------
__device__ __forceinline__ uint32_t pack_h2(__half a, __half b) {
    return (uint32_t)__half_as_ushort(a) | ((uint32_t)__half_as_ushort(b) << 16);
}

__global__ void to_f16(const float* __restrict__ in, __half* __restrict__ hi, int n4)
{
    int i = blockIdx.x * blockDim.x + threadIdx.x;
    if (i >= n4) return;
    float4 v = ((const float4*)in)[i];
    ((uint2*)hi)[i] = make_uint2(
        pack_h2(__float2half_rn(v.x), __float2half_rn(v.y)),
        pack_h2(__float2half_rn(v.z), __float2half_rn(v.w)));
}

// ---------------- analytic Gaussian attention = fixed 15-tap conv -------------
__device__ __forceinline__ float gw(int d) {
    int a = d < 0 ? -d : d;
    switch (a) {
        case 0: return 1.0f;
        case 1: return 0.60653065971e0f;
        case 2: return 0.13533528324e0f;
        case 3: return 1.11089965382e-2f;
        case 4: return 3.35462627903e-4f;
        case 5: return 3.72665317208e-6f;
        case 6: return 1.52299797447e-8f;
        default: return 2.28973484867e-11f;
    }
}

// v (fp16) -> attended (fp16); fp32 accumulation of the 15 taps.
__global__ void conv_attn_f16(const __half* __restrict__ v, __half* __restrict__ att)
{
    const int h  = blockIdx.y;
    const int b  = blockIdx.z;
    const int q  = blockIdx.x * blockDim.y + threadIdx.y;
    const int p4 = threadIdx.x;              // 0..31, 4 halves each

    int c;
    switch (h) {
        case 0: case 5: c = q;        break;
        case 1: case 6: c = q - 1;    break;
        case 2: case 7: c = q + 1;    break;
        case 3:         c = 0;        break;
        default:        c = LSEQ - 1; break;
    }

    float Z = 0.0f;
#pragma unroll
    for (int d = -RAD; d <= RAD; d++) {
        int k = c + d;
        if (k >= 0 && k < LSEQ) Z += gw(d);
    }
    const float invZ = 1.0f / Z;

    const __half* base = v + (size_t)b * LSEQ * NDIM + h * PDIM + p4 * 4;
    float a0 = 0.f, a1 = 0.f, a2 = 0.f, a3 = 0.f;
#pragma unroll
    for (int d = -RAD; d <= RAD; d++) {
        int k = c + d;
        if (k >= 0 && k < LSEQ) {
            float w = gw(d) * invZ;
            uint2 raw = *(const uint2*)(base + (size_t)k * NDIM);
            __half2 v01 = *(__half2*)&raw.x;
            __half2 v23 = *(__half2*)&raw.y;
            float2 f01 = __half22float2(v01);
            float2 f23 = __half22float2(v23);
            a0 = fmaf(w, f01.x, a0);
            a1 = fmaf(w, f01.y, a1);
            a2 = fmaf(w, f23.x, a2);
            a3 = fmaf(w, f23.y, a3);
        }
    }
    size_t oi = (((size_t)b * LSEQ + q) * NDIM + h * PDIM + p4 * 4) / 4; // uint2 idx
    __half2 o01 = __floats2half2_rn(a0, a1);
    __half2 o23 = __floats2half2_rn(a2, a3);
    ((uint2*)att)[oi] = make_uint2(*(uint32_t*)&o01, *(uint32_t*)&o23);
}

// ---------------- launcher ----------------
extern "C" void kernel_launch(void* const* d_in, const int* in_sizes, int n_in,
                              void* d_out, int out_size)
{
    const float* x     = (const float*)d_in[0];
    const float* W_in  = (const float*)d_in[1];
    const float* W_out = (const float*)d_in[2];
    float* out = (float*)d_out;

    __half *vh,*xh,*ah,*wih,*woh;
    cudaGetSymbolAddress((void**)&vh,  g_vh);
    cudaGetSymbolAddress((void**)&xh,  g_xh);
    cudaGetSymbolAddress((void**)&ah,  g_ah);
    cudaGetSymbolAddress((void**)&wih, g_wih);
    cudaGetSymbolAddress((void**)&woh, g_woh);

    cudaFuncSetAttribute(gemm_f16<__half>, cudaFuncAttributeMaxDynamicSharedMemorySize, SMEM_TOTAL);
    cudaFuncSetAttribute(gemm_f16<float>,  cudaFuncAttributeMaxDynamicSharedMemorySize, SMEM_TOTAL);

    const int nx4 = MDIM * KDIM / 4;
    const int nw4 = NDIM * KDIM / 4;
    to_f16<<<(nx4 + 255) / 256, 256>>>(x,     xh,  nx4);
    to_f16<<<(nw4 + 255) / 256, 256>>>(W_in,  wih, nw4);
    to_f16<<<(nw4 + 255) / 256, 256>>>(W_out, woh, nw4);

    dim3 ggrid(NDIM / BT, MDIM / BT);   // (8, 128)
    gemm_f16<__half><<<ggrid, 128, SMEM_TOTAL>>>(xh, wih, vh);

    conv_attn_f16<<<dim3(LSEQ / 8, NHEADS, 8), dim3(32, 8)>>>(vh, ah);

    gemm_f16<float><<<ggrid, 128, SMEM_TOTAL>>>(ah, woh, out);
}